// round 2
// baseline (speedup 1.0000x reference)
#include <cuda_runtime.h>
#include <cstdint>

#define D 64
#define D4 16  // D/4 float4 chunks per row
#define MAX_USERS 200000
#define MAX_SPOTS 50000
#define MAX_NODES (MAX_USERS + MAX_SPOTS)

// Scratch (static device globals — allocation-free per harness rules)
__device__ int   g_deg[MAX_NODES];
__device__ float g_inv[MAX_NODES];

// ---------------------------------------------------------------------------
// Vector reduction (no-return atomic add), sm_90+: 16B coalesced scatter-add
// ---------------------------------------------------------------------------
__device__ __forceinline__ void red_add_v4(float* p, float4 v) {
    asm volatile("red.global.add.v4.f32 [%0], {%1, %2, %3, %4};"
                 :: "l"(p), "f"(v.x), "f"(v.y), "f"(v.z), "f"(v.w)
                 : "memory");
}

// ---------------------------------------------------------------------------
// 1) Zero output buffer (poisoned by harness) and degree scratch
// ---------------------------------------------------------------------------
__global__ void init_kernel(float4* __restrict__ out4, int n_out4, int n_nodes) {
    int i = blockIdx.x * blockDim.x + threadIdx.x;
    int stride = gridDim.x * blockDim.x;
    float4 z = make_float4(0.f, 0.f, 0.f, 0.f);
    for (int j = i; j < n_out4; j += stride) out4[j] = z;
    for (int j = i; j < n_nodes; j += stride) g_deg[j] = 0;
}

// ---------------------------------------------------------------------------
// 2) Degree counting: one thread per edge, 2 integer reductions
// ---------------------------------------------------------------------------
__global__ void degree_kernel(const int* __restrict__ uidx,
                              const int* __restrict__ sidx,
                              int n_edges, int n_users) {
    int i = blockIdx.x * blockDim.x + threadIdx.x;
    if (i >= n_edges) return;
    atomicAdd(&g_deg[uidx[i]], 1);
    atomicAdd(&g_deg[n_users + sidx[i]], 1);
}

// ---------------------------------------------------------------------------
// 3) inv_sqrt(degree), with isolated-node epsilon matching reference
// ---------------------------------------------------------------------------
__global__ void invsqrt_kernel(int n_nodes) {
    int i = blockIdx.x * blockDim.x + threadIdx.x;
    if (i >= n_nodes) return;
    float d = (float)g_deg[i];
    if (d == 0.0f) d = 1e-6f;
    g_inv[i] = rsqrtf(d);
}

// ---------------------------------------------------------------------------
// 4) Edge kernel: 16 threads per edge, each handles one float4 chunk of D=64.
//    Gathers both endpoint rows, pre-normalizes by source inv-sqrt-degree,
//    scatter-adds into the opposite side via vector reductions.
//    Same-address scalar loads (idx, inv) within a 16-lane group are a single
//    L1 broadcast wavefront — no explicit shuffle needed.
// ---------------------------------------------------------------------------
__global__ void edge_kernel(const float4* __restrict__ ux,
                            const float4* __restrict__ sx,
                            const int* __restrict__ uidx,
                            const int* __restrict__ sidx,
                            float* __restrict__ uout,
                            float* __restrict__ sout,
                            int n_edges, int n_users) {
    int t = blockIdx.x * blockDim.x + threadIdx.x;
    int e = t >> 4;        // edge index
    int c = t & 15;        // float4 chunk within the 64-float row
    if (e >= n_edges) return;

    int u = __ldg(uidx + e);
    int s = __ldg(sidx + e);
    float iu = g_inv[u];
    float is = g_inv[n_users + s];

    float4 a = __ldg(ux + u * D4 + c);   // user row chunk
    float4 b = __ldg(sx + s * D4 + c);   // spot row chunk

    float4 m_us = make_float4(a.x * iu, a.y * iu, a.z * iu, a.w * iu); // user -> spot
    float4 m_su = make_float4(b.x * is, b.y * is, b.z * is, b.w * is); // spot -> user

    red_add_v4(sout + s * D + c * 4, m_us);
    red_add_v4(uout + u * D + c * 4, m_su);
}

// ---------------------------------------------------------------------------
// 5) Post-normalize by destination inv-sqrt-degree.
//    Output layout [user_out ‖ spot_out] matches g_inv layout [user ‖ spot],
//    so this is one contiguous streaming pass.
// ---------------------------------------------------------------------------
__global__ void post_kernel(float4* __restrict__ out4, int n_nodes) {
    int t = blockIdx.x * blockDim.x + threadIdx.x;
    if (t >= n_nodes * D4) return;
    float inv = g_inv[t >> 4];
    float4 v = out4[t];
    v.x *= inv; v.y *= inv; v.z *= inv; v.w *= inv;
    out4[t] = v;
}

// ---------------------------------------------------------------------------
extern "C" void kernel_launch(void* const* d_in, const int* in_sizes, int n_in,
                              void* d_out, int out_size) {
    const float* ux   = (const float*)d_in[0];   // user_x [n_users, 64]
    const float* sx   = (const float*)d_in[1];   // spot_x [n_spots, 64]
    const int*   uidx = (const int*)d_in[2];     // user_idx [E]
    const int*   sidx = (const int*)d_in[3];     // spot_idx [E]

    int n_users = in_sizes[0] / D;
    int n_spots = in_sizes[1] / D;
    int n_edges = in_sizes[2];
    int n_nodes = n_users + n_spots;

    float* uout = (float*)d_out;
    float* sout = uout + (size_t)n_users * D;

    // 1) zero outputs + degree scratch
    init_kernel<<<4096, 256>>>((float4*)d_out, out_size / 4, n_nodes);

    // 2) degrees
    degree_kernel<<<(n_edges + 255) / 256, 256>>>(uidx, sidx, n_edges, n_users);

    // 3) rsqrt
    invsqrt_kernel<<<(n_nodes + 255) / 256, 256>>>(n_nodes);

    // 4) edge gather / scale / vector scatter-add
    {
        long long threads = (long long)n_edges * D4;
        int blocks = (int)((threads + 255) / 256);
        edge_kernel<<<blocks, 256>>>((const float4*)ux, (const float4*)sx,
                                     uidx, sidx, uout, sout, n_edges, n_users);
    }

    // 5) post-normalize
    {
        long long threads = (long long)n_nodes * D4;
        int blocks = (int)((threads + 255) / 256);
        post_kernel<<<blocks, 256>>>((float4*)d_out, n_nodes);
    }
}

// round 3
// speedup vs baseline: 1.0008x; 1.0008x over previous
#include <cuda_runtime.h>
#include <cstdint>

#define D 64
#define D4 16  // D/4 float4 chunks per row
#define MAX_USERS 200000
#define MAX_SPOTS 50000
#define MAX_NODES (MAX_USERS + MAX_SPOTS)

// Scratch (static device globals — allocation-free per harness rules)
__device__ int   g_deg[MAX_NODES];
__device__ float g_inv[MAX_NODES];

// ---------------------------------------------------------------------------
// Vector reduction (no-return atomic add), sm_90+: 16B coalesced scatter-add
// ---------------------------------------------------------------------------
__device__ __forceinline__ void red_add_v4(float* p, float4 v) {
    asm volatile("red.global.add.v4.f32 [%0], {%1, %2, %3, %4};"
                 :: "l"(p), "f"(v.x), "f"(v.y), "f"(v.z), "f"(v.w)
                 : "memory");
}

// ---------------------------------------------------------------------------
// 1) Zero output buffer (poisoned by harness) and degree scratch
// ---------------------------------------------------------------------------
__global__ void init_kernel(float4* __restrict__ out4, int n_out4, int n_nodes) {
    int i = blockIdx.x * blockDim.x + threadIdx.x;
    int stride = gridDim.x * blockDim.x;
    float4 z = make_float4(0.f, 0.f, 0.f, 0.f);
    for (int j = i; j < n_out4; j += stride) out4[j] = z;
    for (int j = i; j < n_nodes; j += stride) g_deg[j] = 0;
}

// ---------------------------------------------------------------------------
// 2) Degree counting: one thread per edge, 2 integer reductions
// ---------------------------------------------------------------------------
__global__ void degree_kernel(const int* __restrict__ uidx,
                              const int* __restrict__ sidx,
                              int n_edges, int n_users) {
    int i = blockIdx.x * blockDim.x + threadIdx.x;
    if (i >= n_edges) return;
    atomicAdd(&g_deg[uidx[i]], 1);
    atomicAdd(&g_deg[n_users + sidx[i]], 1);
}

// ---------------------------------------------------------------------------
// 3) inv_sqrt(degree), with isolated-node epsilon matching reference
// ---------------------------------------------------------------------------
__global__ void invsqrt_kernel(int n_nodes) {
    int i = blockIdx.x * blockDim.x + threadIdx.x;
    if (i >= n_nodes) return;
    float d = (float)g_deg[i];
    if (d == 0.0f) d = 1e-6f;
    g_inv[i] = rsqrtf(d);
}

// ---------------------------------------------------------------------------
// 4) Edge kernel: 16 threads per edge, each handles one float4 chunk of D=64.
//    Gathers both endpoint rows, pre-normalizes by source inv-sqrt-degree,
//    scatter-adds into the opposite side via vector reductions.
//    Same-address scalar loads (idx, inv) within a 16-lane group are a single
//    L1 broadcast wavefront — no explicit shuffle needed.
// ---------------------------------------------------------------------------
__global__ void edge_kernel(const float4* __restrict__ ux,
                            const float4* __restrict__ sx,
                            const int* __restrict__ uidx,
                            const int* __restrict__ sidx,
                            float* __restrict__ uout,
                            float* __restrict__ sout,
                            int n_edges, int n_users) {
    int t = blockIdx.x * blockDim.x + threadIdx.x;
    int e = t >> 4;        // edge index
    int c = t & 15;        // float4 chunk within the 64-float row
    if (e >= n_edges) return;

    int u = __ldg(uidx + e);
    int s = __ldg(sidx + e);
    float iu = g_inv[u];
    float is = g_inv[n_users + s];

    float4 a = __ldg(ux + u * D4 + c);   // user row chunk
    float4 b = __ldg(sx + s * D4 + c);   // spot row chunk

    float4 m_us = make_float4(a.x * iu, a.y * iu, a.z * iu, a.w * iu); // user -> spot
    float4 m_su = make_float4(b.x * is, b.y * is, b.z * is, b.w * is); // spot -> user

    red_add_v4(sout + s * D + c * 4, m_us);
    red_add_v4(uout + u * D + c * 4, m_su);
}

// ---------------------------------------------------------------------------
// 5) Post-normalize by destination inv-sqrt-degree.
//    Output layout [user_out ‖ spot_out] matches g_inv layout [user ‖ spot],
//    so this is one contiguous streaming pass.
// ---------------------------------------------------------------------------
__global__ void post_kernel(float4* __restrict__ out4, int n_nodes) {
    int t = blockIdx.x * blockDim.x + threadIdx.x;
    if (t >= n_nodes * D4) return;
    float inv = g_inv[t >> 4];
    float4 v = out4[t];
    v.x *= inv; v.y *= inv; v.z *= inv; v.w *= inv;
    out4[t] = v;
}

// ---------------------------------------------------------------------------
extern "C" void kernel_launch(void* const* d_in, const int* in_sizes, int n_in,
                              void* d_out, int out_size) {
    const float* ux   = (const float*)d_in[0];   // user_x [n_users, 64]
    const float* sx   = (const float*)d_in[1];   // spot_x [n_spots, 64]
    const int*   uidx = (const int*)d_in[2];     // user_idx [E]
    const int*   sidx = (const int*)d_in[3];     // spot_idx [E]

    int n_users = in_sizes[0] / D;
    int n_spots = in_sizes[1] / D;
    int n_edges = in_sizes[2];
    int n_nodes = n_users + n_spots;

    float* uout = (float*)d_out;
    float* sout = uout + (size_t)n_users * D;

    // 1) zero outputs + degree scratch
    init_kernel<<<4096, 256>>>((float4*)d_out, out_size / 4, n_nodes);

    // 2) degrees
    degree_kernel<<<(n_edges + 255) / 256, 256>>>(uidx, sidx, n_edges, n_users);

    // 3) rsqrt
    invsqrt_kernel<<<(n_nodes + 255) / 256, 256>>>(n_nodes);

    // 4) edge gather / scale / vector scatter-add
    {
        long long threads = (long long)n_edges * D4;
        int blocks = (int)((threads + 255) / 256);
        edge_kernel<<<blocks, 256>>>((const float4*)ux, (const float4*)sx,
                                     uidx, sidx, uout, sout, n_edges, n_users);
    }

    // 5) post-normalize
    {
        long long threads = (long long)n_nodes * D4;
        int blocks = (int)((threads + 255) / 256);
        post_kernel<<<blocks, 256>>>((float4*)d_out, n_nodes);
    }
}

// round 4
// speedup vs baseline: 1.5372x; 1.5360x over previous
#include <cuda_runtime.h>
#include <cstdint>

#define D 64
#define D4 16
#define MAX_USERS 200000
#define MAX_SPOTS 50000
#define MAX_NODES (MAX_USERS + MAX_SPOTS)
#define MAX_EDGES 3200000

// ---------------------------------------------------------------------------
// Static device scratch (allocation-free per harness rules)
// ---------------------------------------------------------------------------
__device__ int   g_deg[MAX_NODES];
__device__ float g_inv[MAX_NODES];
__device__ int   g_off[MAX_NODES + 1];   // exclusive offsets, users then spots
__device__ int   g_cur[MAX_NODES];       // scatter cursors
__device__ int   g_list[2 * MAX_EDGES];  // adjacency: [0,E) user slots, [E,2E) spot slots
__device__ int   g_bsum[1024];           // scan block sums

// ---------------------------------------------------------------------------
// 0) zero degree counters
// ---------------------------------------------------------------------------
__global__ void zero_deg_kernel(int n_nodes) {
    int i = blockIdx.x * blockDim.x + threadIdx.x;
    if (i < n_nodes) g_deg[i] = 0;
}

// ---------------------------------------------------------------------------
// 1) degree counting (spread-address atomics)
// ---------------------------------------------------------------------------
__global__ void degree_kernel(const int* __restrict__ uidx,
                              const int* __restrict__ sidx,
                              int n_edges, int n_users) {
    int i = blockIdx.x * blockDim.x + threadIdx.x;
    if (i >= n_edges) return;
    atomicAdd(&g_deg[__ldg(uidx + i)], 1);
    atomicAdd(&g_deg[n_users + __ldg(sidx + i)], 1);
}

// ---------------------------------------------------------------------------
// 2) scan pass 1: per-block (1024 elems) exclusive scan + block sums
// ---------------------------------------------------------------------------
__global__ void scan_pass1(int n) {
    __shared__ int warp_tot[8];
    int blk = blockIdx.x, t = threadIdx.x;
    int base = blk * 1024 + t * 4;

    int v0 = 0, v1 = 0, v2 = 0, v3 = 0;
    if (base + 3 < n) {
        int4 q = *(const int4*)(g_deg + base);
        v0 = q.x; v1 = q.y; v2 = q.z; v3 = q.w;
    } else {
        if (base     < n) v0 = g_deg[base];
        if (base + 1 < n) v1 = g_deg[base + 1];
        if (base + 2 < n) v2 = g_deg[base + 2];
        if (base + 3 < n) v3 = g_deg[base + 3];
    }
    int s = v0 + v1 + v2 + v3;

    // warp inclusive scan of per-thread sums
    int inc = s;
    #pragma unroll
    for (int o = 1; o < 32; o <<= 1) {
        int x = __shfl_up_sync(0xffffffffu, inc, o);
        if ((t & 31) >= o) inc += x;
    }
    if ((t & 31) == 31) warp_tot[t >> 5] = inc;
    __syncthreads();
    if (t < 8) {
        int w = warp_tot[t];
        #pragma unroll
        for (int o = 1; o < 8; o <<= 1) {
            int x = __shfl_up_sync(0xffu, w, o);
            if (t >= o) w += x;
        }
        warp_tot[t] = w;  // inclusive warp totals
    }
    __syncthreads();

    int warp_excl = (t >= 32) ? warp_tot[(t >> 5) - 1] : 0;
    int te = warp_excl + inc - s;  // exclusive prefix of this thread

    if (base     < n) g_off[base]     = te;
    if (base + 1 < n) g_off[base + 1] = te + v0;
    if (base + 2 < n) g_off[base + 2] = te + v0 + v1;
    if (base + 3 < n) g_off[base + 3] = te + v0 + v1 + v2;

    if (t == 0) g_bsum[blk] = warp_tot[7];  // block total
}

// ---------------------------------------------------------------------------
// 3) scan pass 2: single block exclusive scan of block sums (nb <= 1024)
// ---------------------------------------------------------------------------
__global__ void scan_pass2(int nb) {
    __shared__ int sm[1024];
    int t = threadIdx.x;
    int v = (t < nb) ? g_bsum[t] : 0;
    sm[t] = v;
    __syncthreads();
    #pragma unroll
    for (int o = 1; o < 1024; o <<= 1) {
        int x = (t >= o) ? sm[t - o] : 0;
        __syncthreads();
        sm[t] += x;
        __syncthreads();
    }
    if (t < nb) g_bsum[t] = sm[t] - v;  // exclusive
}

// ---------------------------------------------------------------------------
// 4) scan pass 3: add block bases, init cursors, compute inv-sqrt degrees
// ---------------------------------------------------------------------------
__global__ void scan_pass3(int n, int total) {
    int i = blockIdx.x * blockDim.x + threadIdx.x;
    if (i == 0) g_off[n] = total;
    if (i >= n) return;
    int o = g_off[i] + g_bsum[i >> 10];
    g_off[i] = o;
    g_cur[i] = o;
    float d = (float)g_deg[i];
    g_inv[i] = rsqrtf(d == 0.0f ? 1e-6f : d);
}

// ---------------------------------------------------------------------------
// 5) scatter edges into per-destination adjacency lists
// ---------------------------------------------------------------------------
__global__ void scatter_kernel(const int* __restrict__ uidx,
                               const int* __restrict__ sidx,
                               int n_edges, int n_users) {
    int e = blockIdx.x * blockDim.x + threadIdx.x;
    if (e >= n_edges) return;
    int u = __ldg(uidx + e);
    int s = __ldg(sidx + e);
    int pu = atomicAdd(&g_cur[u], 1);
    g_list[pu] = s;                 // user's neighbor list holds spot ids
    int ps = atomicAdd(&g_cur[n_users + s], 1);
    g_list[ps] = u;                 // spot's neighbor list holds user ids
}

// ---------------------------------------------------------------------------
// 6) gather: 16 lanes per node, register accumulation, single store.
//    out[node] = inv[node] * sum_{v in N(node)} inv[v_global] * x_src[v]
// ---------------------------------------------------------------------------
__global__ void gather_kernel(const float4* __restrict__ ux,
                              const float4* __restrict__ sx,
                              float4* __restrict__ out,
                              int n_nodes, int n_users) {
    int t = blockIdx.x * blockDim.x + threadIdx.x;
    int node = t >> 4;
    int c = t & 15;
    if (node >= n_nodes) return;

    int beg = g_off[node];
    int end = g_off[node + 1];

    bool is_user = node < n_users;
    const float4* src  = is_user ? sx : ux;
    const float*  winv = is_user ? (g_inv + n_users) : g_inv;

    float4 acc = make_float4(0.f, 0.f, 0.f, 0.f);
    #pragma unroll 4
    for (int j = beg; j < end; ++j) {
        int v = __ldg(g_list + j);                 // broadcast within 16-lane group
        float w = __ldg(winv + v);                 // broadcast
        float4 r = __ldg(src + (size_t)v * D4 + c);
        acc.x += w * r.x;
        acc.y += w * r.y;
        acc.z += w * r.z;
        acc.w += w * r.w;
    }
    float si = g_inv[node];
    out[(size_t)node * D4 + c] =
        make_float4(acc.x * si, acc.y * si, acc.z * si, acc.w * si);
}

// ---------------------------------------------------------------------------
extern "C" void kernel_launch(void* const* d_in, const int* in_sizes, int n_in,
                              void* d_out, int out_size) {
    const float* ux   = (const float*)d_in[0];
    const float* sx   = (const float*)d_in[1];
    const int*   uidx = (const int*)d_in[2];
    const int*   sidx = (const int*)d_in[3];

    int n_users = in_sizes[0] / D;
    int n_spots = in_sizes[1] / D;
    int n_edges = in_sizes[2];
    int n_nodes = n_users + n_spots;

    // 0) zero degrees
    zero_deg_kernel<<<(n_nodes + 255) / 256, 256>>>(n_nodes);

    // 1) degrees
    degree_kernel<<<(n_edges + 255) / 256, 256>>>(uidx, sidx, n_edges, n_users);

    // 2-4) exclusive scan of degrees -> offsets, cursors, inv-sqrt
    int nblocks = (n_nodes + 1023) / 1024;
    scan_pass1<<<nblocks, 256>>>(n_nodes);
    scan_pass2<<<1, 1024>>>(nblocks);
    scan_pass3<<<(n_nodes + 255) / 256, 256>>>(n_nodes, 2 * n_edges);

    // 5) adjacency build
    scatter_kernel<<<(n_edges + 255) / 256, 256>>>(uidx, sidx, n_edges, n_users);

    // 6) gather + fused post-normalize (fully writes output; no zeroing pass)
    {
        long long threads = (long long)n_nodes * D4;
        int blocks = (int)((threads + 255) / 256);
        gather_kernel<<<blocks, 256>>>((const float4*)ux, (const float4*)sx,
                                       (float4*)d_out, n_nodes, n_users);
    }
}

// round 5
// speedup vs baseline: 1.7346x; 1.1284x over previous
#include <cuda_runtime.h>
#include <cuda_fp16.h>
#include <cstdint>

#define D 64
#define D4 16
#define MAX_USERS 200000
#define MAX_SPOTS 50000
#define MAX_NODES (MAX_USERS + MAX_SPOTS)
#define MAX_EDGES 3200000

// ---------------------------------------------------------------------------
// Static device scratch (allocation-free per harness rules)
// ---------------------------------------------------------------------------
__device__ int     g_deg[MAX_NODES];
__device__ float   g_inv[MAX_NODES];
__device__ int     g_off[MAX_NODES + 1];
__device__ int     g_cur[MAX_NODES];
__device__ int     g_list[2 * MAX_EDGES];     // global-id neighbor lists
__device__ int     g_bsum[1024];
__device__ __half2 g_feat[MAX_NODES * 32];    // pre-scaled fp16 features (128 B/node)

// ---------------------------------------------------------------------------
// 0) zero degree counters
// ---------------------------------------------------------------------------
__global__ void zero_deg_kernel(int n_nodes) {
    int i = blockIdx.x * blockDim.x + threadIdx.x;
    if (i < n_nodes) g_deg[i] = 0;
}

// ---------------------------------------------------------------------------
// 1) degree counting
// ---------------------------------------------------------------------------
__global__ void degree_kernel(const int* __restrict__ uidx,
                              const int* __restrict__ sidx,
                              int n_edges, int n_users) {
    int i = blockIdx.x * blockDim.x + threadIdx.x;
    if (i >= n_edges) return;
    atomicAdd(&g_deg[__ldg(uidx + i)], 1);
    atomicAdd(&g_deg[n_users + __ldg(sidx + i)], 1);
}

// ---------------------------------------------------------------------------
// 2) scan pass 1: per-1024-chunk exclusive scan + block sums
// ---------------------------------------------------------------------------
__global__ void scan_pass1(int n) {
    __shared__ int warp_tot[8];
    int blk = blockIdx.x, t = threadIdx.x;
    int base = blk * 1024 + t * 4;

    int v0 = 0, v1 = 0, v2 = 0, v3 = 0;
    if (base + 3 < n) {
        int4 q = *(const int4*)(g_deg + base);
        v0 = q.x; v1 = q.y; v2 = q.z; v3 = q.w;
    } else {
        if (base     < n) v0 = g_deg[base];
        if (base + 1 < n) v1 = g_deg[base + 1];
        if (base + 2 < n) v2 = g_deg[base + 2];
        if (base + 3 < n) v3 = g_deg[base + 3];
    }
    int s = v0 + v1 + v2 + v3;

    int inc = s;
    #pragma unroll
    for (int o = 1; o < 32; o <<= 1) {
        int x = __shfl_up_sync(0xffffffffu, inc, o);
        if ((t & 31) >= o) inc += x;
    }
    if ((t & 31) == 31) warp_tot[t >> 5] = inc;
    __syncthreads();
    if (t < 8) {
        int w = warp_tot[t];
        #pragma unroll
        for (int o = 1; o < 8; o <<= 1) {
            int x = __shfl_up_sync(0xffu, w, o);
            if (t >= o) w += x;
        }
        warp_tot[t] = w;
    }
    __syncthreads();

    int warp_excl = (t >= 32) ? warp_tot[(t >> 5) - 1] : 0;
    int te = warp_excl + inc - s;

    if (base     < n) g_off[base]     = te;
    if (base + 1 < n) g_off[base + 1] = te + v0;
    if (base + 2 < n) g_off[base + 2] = te + v0 + v1;
    if (base + 3 < n) g_off[base + 3] = te + v0 + v1 + v2;

    if (t == 0) g_bsum[blk] = warp_tot[7];
}

// ---------------------------------------------------------------------------
// 3) scan pass 2: single-block scan of block sums
// ---------------------------------------------------------------------------
__global__ void scan_pass2(int nb) {
    __shared__ int sm[1024];
    int t = threadIdx.x;
    int v = (t < nb) ? g_bsum[t] : 0;
    sm[t] = v;
    __syncthreads();
    #pragma unroll
    for (int o = 1; o < 1024; o <<= 1) {
        int x = (t >= o) ? sm[t - o] : 0;
        __syncthreads();
        sm[t] += x;
        __syncthreads();
    }
    if (t < nb) g_bsum[t] = sm[t] - v;
}

// ---------------------------------------------------------------------------
// 4) scan pass 3: finalize offsets, cursors, inv-sqrt degrees
// ---------------------------------------------------------------------------
__global__ void scan_pass3(int n, int total) {
    int i = blockIdx.x * blockDim.x + threadIdx.x;
    if (i == 0) g_off[n] = total;
    if (i >= n) return;
    int o = g_off[i] + g_bsum[i >> 10];
    g_off[i] = o;
    g_cur[i] = o;
    float d = (float)g_deg[i];
    g_inv[i] = rsqrtf(d == 0.0f ? 1e-6f : d);
}

// ---------------------------------------------------------------------------
// 5) convert: pre-scaled fp16 features, global-id indexed.
//    g_feat[v] = fp16( x[v] * inv[v] ), 8 fp32 -> 8 fp16 per thread.
// ---------------------------------------------------------------------------
__global__ void convert_kernel(const float4* __restrict__ ux,
                               const float4* __restrict__ sx,
                               int n_nodes, int n_users) {
    int t = blockIdx.x * blockDim.x + threadIdx.x;
    int node = t >> 3;
    int c = t & 7;
    if (node >= n_nodes) return;

    float inv = g_inv[node];
    const float4* src = (node < n_users)
        ? (ux + (size_t)node * D4)
        : (sx + (size_t)(node - n_users) * D4);
    float4 a = __ldg(src + c * 2);
    float4 b = __ldg(src + c * 2 + 1);

    __half2 h0 = __floats2half2_rn(a.x * inv, a.y * inv);
    __half2 h1 = __floats2half2_rn(a.z * inv, a.w * inv);
    __half2 h2 = __floats2half2_rn(b.x * inv, b.y * inv);
    __half2 h3 = __floats2half2_rn(b.z * inv, b.w * inv);

    uint4 v;
    v.x = *reinterpret_cast<unsigned*>(&h0);
    v.y = *reinterpret_cast<unsigned*>(&h1);
    v.z = *reinterpret_cast<unsigned*>(&h2);
    v.w = *reinterpret_cast<unsigned*>(&h3);
    reinterpret_cast<uint4*>(g_feat)[(size_t)node * 8 + c] = v;
}

// ---------------------------------------------------------------------------
// 6) scatter edges into global-id adjacency lists
// ---------------------------------------------------------------------------
__global__ void scatter_kernel(const int* __restrict__ uidx,
                               const int* __restrict__ sidx,
                               int n_edges, int n_users) {
    int e = blockIdx.x * blockDim.x + threadIdx.x;
    if (e >= n_edges) return;
    int u = __ldg(uidx + e);
    int s = __ldg(sidx + e);
    int pu = atomicAdd(&g_cur[u], 1);
    g_list[pu] = n_users + s;            // user's neighbors: spot global ids
    int ps = atomicAdd(&g_cur[n_users + s], 1);
    g_list[ps] = u;                      // spot's neighbors: user global ids
}

// ---------------------------------------------------------------------------
// 7) gather: 8 lanes per node over 128 B fp16 rows, fp32 accumulation,
//    fused dest-scale, single store pass.
// ---------------------------------------------------------------------------
__global__ void gather_kernel(float4* __restrict__ out, int n_nodes) {
    int t = blockIdx.x * blockDim.x + threadIdx.x;
    int node = t >> 3;
    int c = t & 7;
    if (node >= n_nodes) return;

    int beg = g_off[node];
    int end = g_off[node + 1];

    const uint4* feat = reinterpret_cast<const uint4*>(g_feat);

    float a0 = 0.f, a1 = 0.f, a2 = 0.f, a3 = 0.f;
    float a4 = 0.f, a5 = 0.f, a6 = 0.f, a7 = 0.f;

    #pragma unroll 4
    for (int j = beg; j < end; ++j) {
        int g = __ldg(g_list + j);                       // broadcast in 8-lane group
        uint4 q = __ldg(feat + (size_t)g * 8 + c);
        float2 f0 = __half22float2(*reinterpret_cast<__half2*>(&q.x));
        float2 f1 = __half22float2(*reinterpret_cast<__half2*>(&q.y));
        float2 f2 = __half22float2(*reinterpret_cast<__half2*>(&q.z));
        float2 f3 = __half22float2(*reinterpret_cast<__half2*>(&q.w));
        a0 += f0.x; a1 += f0.y;
        a2 += f1.x; a3 += f1.y;
        a4 += f2.x; a5 += f2.y;
        a6 += f3.x; a7 += f3.y;
    }

    float si = g_inv[node];
    float4 o0 = make_float4(a0 * si, a1 * si, a2 * si, a3 * si);
    float4 o1 = make_float4(a4 * si, a5 * si, a6 * si, a7 * si);
    size_t base = (size_t)node * D4 + c * 2;
    out[base]     = o0;
    out[base + 1] = o1;
}

// ---------------------------------------------------------------------------
extern "C" void kernel_launch(void* const* d_in, const int* in_sizes, int n_in,
                              void* d_out, int out_size) {
    const float* ux   = (const float*)d_in[0];
    const float* sx   = (const float*)d_in[1];
    const int*   uidx = (const int*)d_in[2];
    const int*   sidx = (const int*)d_in[3];

    int n_users = in_sizes[0] / D;
    int n_spots = in_sizes[1] / D;
    int n_edges = in_sizes[2];
    int n_nodes = n_users + n_spots;

    zero_deg_kernel<<<(n_nodes + 255) / 256, 256>>>(n_nodes);
    degree_kernel<<<(n_edges + 255) / 256, 256>>>(uidx, sidx, n_edges, n_users);

    int nblocks = (n_nodes + 1023) / 1024;
    scan_pass1<<<nblocks, 256>>>(n_nodes);
    scan_pass2<<<1, 1024>>>(nblocks);
    scan_pass3<<<(n_nodes + 255) / 256, 256>>>(n_nodes, 2 * n_edges);

    // pre-scaled fp16 feature table (global-id indexed)
    {
        long long threads = (long long)n_nodes * 8;
        int blocks = (int)((threads + 255) / 256);
        convert_kernel<<<blocks, 256>>>((const float4*)ux, (const float4*)sx,
                                        n_nodes, n_users);
    }

    scatter_kernel<<<(n_edges + 255) / 256, 256>>>(uidx, sidx, n_edges, n_users);

    {
        long long threads = (long long)n_nodes * 8;
        int blocks = (int)((threads + 255) / 256);
        gather_kernel<<<blocks, 256>>>((float4*)d_out, n_nodes);
    }
}